// round 1
// baseline (speedup 1.0000x reference)
#include <cuda_runtime.h>

// SSIM loss, fused separable 11x11 Gaussian depthwise conv.
// Inputs: img1, img2 : [32,3,512,512] fp32. Output: scalar float = 1 - mean(ssim_map).

#define PLANE      512
#define TW         64          // tile output width
#define TH         48          // tile output height
#define VCOLS      74          // TW + 10 (x halo)
#define VSTRIDE    75          // smem row stride (odd -> fewer conflicts)
#define NTHREADS   224
#define NTILE_X    8           // 512/64
#define NTILE_Y    11          // ceil(512/48)
#define NPLANES    96          // 32*3
#define NPART      (NTILE_X*NTILE_Y*NPLANES)

__device__ float g_partial[NPART];

// Gaussian(11, sigma=1.5), normalized. Compile-time literals -> FFMA-imm (rt=1).
__device__ __forceinline__ float gw(int k) {
    constexpr float KW[11] = {
        0.0010284f, 0.0075988f, 0.0360008f, 0.1093607f, 0.2130055f,
        0.2660117f,
        0.2130055f, 0.1093607f, 0.0360008f, 0.0075988f, 0.0010284f
    };
    return KW[k];
}

__global__ void __launch_bounds__(NTHREADS)
ssim_kernel(const float* __restrict__ img1, const float* __restrict__ img2)
{
    extern __shared__ float sm[];   // 5 * TH * VSTRIDE floats = 72000 B
    float* smF[5];
    #pragma unroll
    for (int f = 0; f < 5; ++f) smF[f] = sm + f * (TH * VSTRIDE);

    const int tid = threadIdx.x;
    const int x0  = blockIdx.x * TW;
    const int y0  = blockIdx.y * TH;
    const float* __restrict__ p1 = img1 + (size_t)blockIdx.z * (PLANE * PLANE);
    const float* __restrict__ p2 = img2 + (size_t)blockIdx.z * (PLANE * PLANE);

    // ---------------- Vertical pass (global -> smem), 5 fields ----------------
    // 222 tasks: column c (0..73) x strip (0..2), strip = 16 output rows.
    if (tid < VCOLS * 3) {
        const int c     = tid % VCOLS;
        const int strip = tid / VCOLS;
        const int gx    = x0 + c - 5;
        const bool xok  = ((unsigned)gx < (unsigned)PLANE);
        const int ybase = y0 + strip * 16 - 5;

        float m1[16], m2[16], e11[16], e22[16], e12[16];
        #pragma unroll
        for (int r = 0; r < 16; ++r) { m1[r]=0.f; m2[r]=0.f; e11[r]=0.f; e22[r]=0.f; e12[r]=0.f; }

        #pragma unroll
        for (int j = 0; j < 26; ++j) {
            const int gy = ybase + j;
            const bool ok = xok && ((unsigned)gy < (unsigned)PLANE);
            const int idx = gy * PLANE + gx;
            float a1 = ok ? __ldg(p1 + idx) : 0.f;
            float a2 = ok ? __ldg(p2 + idx) : 0.f;
            float q1  = a1 * a1;
            float q2  = a2 * a2;
            float q12 = a1 * a2;
            #pragma unroll
            for (int k = 0; k < 11; ++k) {
                const int o = j - k;
                if (o >= 0 && o < 16) {
                    m1[o]  = fmaf(gw(k), a1,  m1[o]);
                    m2[o]  = fmaf(gw(k), a2,  m2[o]);
                    e11[o] = fmaf(gw(k), q1,  e11[o]);
                    e22[o] = fmaf(gw(k), q2,  e22[o]);
                    e12[o] = fmaf(gw(k), q12, e12[o]);
                }
            }
        }
        #pragma unroll
        for (int r = 0; r < 16; ++r) {
            const int row = strip * 16 + r;
            smF[0][row * VSTRIDE + c] = m1[r];
            smF[1][row * VSTRIDE + c] = m2[r];
            smF[2][row * VSTRIDE + c] = e11[r];
            smF[3][row * VSTRIDE + c] = e22[r];
            smF[4][row * VSTRIDE + c] = e12[r];
        }
    }
    __syncthreads();

    // ---------------- Horizontal pass (smem -> SSIM map -> local sum) --------
    // 192 tasks: row (0..47) x segment (0..3), segment = 16 output cols.
    float sum = 0.f;
    if (tid < TH * 4) {
        const int row = tid >> 2;
        const int seg = tid & 3;
        const int c0  = seg * 16;
        const float* r0 = smF[0] + row * VSTRIDE + c0;
        const float* r1 = smF[1] + row * VSTRIDE + c0;
        const float* r2 = smF[2] + row * VSTRIDE + c0;
        const float* r3 = smF[3] + row * VSTRIDE + c0;
        const float* r4 = smF[4] + row * VSTRIDE + c0;

        float m1[16], m2[16], e11[16], e22[16], e12[16];
        #pragma unroll
        for (int o = 0; o < 16; ++o) { m1[o]=0.f; m2[o]=0.f; e11[o]=0.f; e22[o]=0.f; e12[o]=0.f; }

        #pragma unroll
        for (int j = 0; j < 26; ++j) {
            float b0 = r0[j];
            float b1 = r1[j];
            float b2 = r2[j];
            float b3 = r3[j];
            float b4 = r4[j];
            #pragma unroll
            for (int k = 0; k < 11; ++k) {
                const int o = j - k;
                if (o >= 0 && o < 16) {
                    m1[o]  = fmaf(gw(k), b0, m1[o]);
                    m2[o]  = fmaf(gw(k), b1, m2[o]);
                    e11[o] = fmaf(gw(k), b2, e11[o]);
                    e22[o] = fmaf(gw(k), b3, e22[o]);
                    e12[o] = fmaf(gw(k), b4, e12[o]);
                }
            }
        }

        const int gy = y0 + row;
        if (gy < PLANE) {
            const float C1 = 0.0001f;   // (0.01)^2
            const float C2 = 0.0009f;   // (0.03)^2
            #pragma unroll
            for (int o = 0; o < 16; ++o) {
                float mu1 = m1[o], mu2 = m2[o];
                float mu1sq = mu1 * mu1;
                float mu2sq = mu2 * mu2;
                float mu12  = mu1 * mu2;
                float s11 = e11[o] - mu1sq;
                float s22 = e22[o] - mu2sq;
                float s12 = e12[o] - mu12;
                float num = (2.f * mu12 + C1) * (2.f * s12 + C2);
                float den = (mu1sq + mu2sq + C1) * (s11 + s22 + C2);
                sum += __fdividef(num, den);
            }
        }
    }

    // ---------------- Block reduction (fixed order, deterministic) -----------
    #pragma unroll
    for (int off = 16; off > 0; off >>= 1)
        sum += __shfl_down_sync(0xffffffffu, sum, off);

    __shared__ float wsum[NTHREADS / 32];
    const int wid = tid >> 5, lane = tid & 31;
    if (lane == 0) wsum[wid] = sum;
    __syncthreads();
    if (tid == 0) {
        float s = 0.f;
        #pragma unroll
        for (int w = 0; w < NTHREADS / 32; ++w) s += wsum[w];
        g_partial[((size_t)blockIdx.z * NTILE_Y + blockIdx.y) * NTILE_X + blockIdx.x] = s;
    }
}

__global__ void __launch_bounds__(256)
ssim_finalize(float* __restrict__ out)
{
    __shared__ double ds[256];
    double s = 0.0;
    for (int i = threadIdx.x; i < NPART; i += 256)
        s += (double)g_partial[i];
    ds[threadIdx.x] = s;
    __syncthreads();
    for (int st = 128; st > 0; st >>= 1) {
        if (threadIdx.x < st) ds[threadIdx.x] += ds[threadIdx.x + st];
        __syncthreads();
    }
    if (threadIdx.x == 0) {
        const double N = 32.0 * 3.0 * 512.0 * 512.0;
        out[0] = (float)(1.0 - ds[0] / N);
    }
}

extern "C" void kernel_launch(void* const* d_in, const int* in_sizes, int n_in,
                              void* d_out, int out_size)
{
    const float* img1 = (const float*)d_in[0];
    const float* img2 = (const float*)d_in[1];
    float* out = (float*)d_out;

    const int smem = 5 * TH * VSTRIDE * (int)sizeof(float);   // 72000 B
    cudaFuncSetAttribute(ssim_kernel, cudaFuncAttributeMaxDynamicSharedMemorySize, smem);

    dim3 grid(NTILE_X, NTILE_Y, NPLANES);
    ssim_kernel<<<grid, NTHREADS, smem>>>(img1, img2);
    ssim_finalize<<<1, 256>>>(out);
}